// round 14
// baseline (speedup 1.0000x reference)
#include <cuda_runtime.h>

#define N_NODES 50000
#define E_EDGES 800000
#define D 128
#define D4 32      // D in float4 units
#define NPB 80     // nodes per tile (10 m-rows per thread)
#define MPT 10     // m rows per thread
#define NTILES ((N_NODES + NPB - 1) / NPB)
#define GTHREADS 512
#define GGRID 152
#define WSTRIDE 65 // float4 per j-pair row in weight smem (odd -> conflict-free)

// smem: wl_s[64*65] | wr_s[64*65] | s_in[NPB*64] | mu[NPB] | rs[NPB]
#define SMEM_F4 (2 * 64 * WSTRIDE + NPB * 64)
#define SMEM_BYTES (SMEM_F4 * 16 + 2 * NPB * 4)

// Scratch (allocation-free rule: __device__ globals)
__device__ float4 g_agg[N_NODES * D4];
__device__ float4 g_h1[N_NODES * D4];
__device__ float4 g_h2[N_NODES * D4];
__device__ int    g_deg[N_NODES];
__device__ int    g_rowptr[N_NODES + 1];
__device__ int    g_cursor[N_NODES];
__device__ int    g_csrc[E_EDGES];

// ---------------------------------------------------------------------------
// packed f32x2 helpers
// ---------------------------------------------------------------------------
__device__ __forceinline__ void fma2(unsigned long long& d,
                                     unsigned long long a,
                                     unsigned long long b) {
    asm("fma.rn.f32x2 %0, %1, %2, %0;" : "+l"(d) : "l"(a), "l"(b));
}
__device__ __forceinline__ unsigned long long pack2(float lo, float hi) {
    unsigned long long r;
    asm("mov.b64 %0, {%1, %2};" : "=l"(r) : "f"(lo), "f"(hi));
    return r;
}
__device__ __forceinline__ float sum2(unsigned long long v) {
    float lo, hi;
    asm("mov.b64 {%0, %1}, %2;" : "=f"(lo), "=f"(hi) : "l"(v));
    return lo + hi;
}

// ---------------------------------------------------------------------------
// dummy kernel: aligns ncu -s 5 onto gemm_persist<0> (launch #6)
// ---------------------------------------------------------------------------
__global__ void dummy_kernel() {
    if (threadIdx.x == 0 && blockIdx.x == 0) g_deg[0] += 0;
}

// ---------------------------------------------------------------------------
// CSR build: memset degrees -> histogram (x4) -> scan (x4) -> fill (x4)
// ---------------------------------------------------------------------------
__global__ void hist_kernel(const int* __restrict__ dst, int E) {
    int t = blockIdx.x * blockDim.x + threadIdx.x;
    int e = t * 4;
    if (e + 3 < E) {
        int4 d = __ldg(reinterpret_cast<const int4*>(dst + e));
        atomicAdd(&g_deg[d.x], 1);
        atomicAdd(&g_deg[d.y], 1);
        atomicAdd(&g_deg[d.z], 1);
        atomicAdd(&g_deg[d.w], 1);
    } else {
        for (; e < E; e++) atomicAdd(&g_deg[__ldg(dst + e)], 1);
    }
}

__device__ __forceinline__ int warp_incl_scan(int v, int lane) {
    #pragma unroll
    for (int o = 1; o < 32; o <<= 1) {
        int t = __shfl_up_sync(0xFFFFFFFFu, v, o);
        if (lane >= o) v += t;
    }
    return v;
}

__global__ void __launch_bounds__(1024) scan_kernel() {
    __shared__ int s_warp[32];
    __shared__ int s_carry;
    int tid = threadIdx.x;
    int lane = tid & 31, wid = tid >> 5;
    if (tid == 0) s_carry = 0;
    __syncthreads();

    for (int base = 0; base < N_NODES; base += 4096) {
        int idx = base + tid * 4;
        int d0 = 0, d1 = 0, d2 = 0, d3 = 0;
        if (idx + 3 < N_NODES) {
            int4 t4 = *reinterpret_cast<const int4*>(g_deg + idx);
            d0 = t4.x; d1 = t4.y; d2 = t4.z; d3 = t4.w;
        } else {
            if (idx + 0 < N_NODES) d0 = g_deg[idx + 0];
            if (idx + 1 < N_NODES) d1 = g_deg[idx + 1];
            if (idx + 2 < N_NODES) d2 = g_deg[idx + 2];
            if (idx + 3 < N_NODES) d3 = g_deg[idx + 3];
        }
        int tsum = d0 + d1 + d2 + d3;
        int incl = warp_incl_scan(tsum, lane);
        if (lane == 31) s_warp[wid] = incl;
        __syncthreads();
        if (wid == 0) {
            int w = s_warp[lane];
            w = warp_incl_scan(w, lane);
            s_warp[lane] = w;
        }
        __syncthreads();
        int off = s_carry + ((wid > 0) ? s_warp[wid - 1] : 0) + incl - tsum;
        int p0 = off, p1 = off + d0, p2 = p1 + d1, p3 = p2 + d2;
        if (idx + 3 < N_NODES) {
            int4 rp = make_int4(p0, p1, p2, p3);
            *reinterpret_cast<int4*>(g_rowptr + idx) = rp;
            *reinterpret_cast<int4*>(g_cursor + idx) = rp;
        } else {
            if (idx + 0 < N_NODES) { g_rowptr[idx + 0] = p0; g_cursor[idx + 0] = p0; }
            if (idx + 1 < N_NODES) { g_rowptr[idx + 1] = p1; g_cursor[idx + 1] = p1; }
            if (idx + 2 < N_NODES) { g_rowptr[idx + 2] = p2; g_cursor[idx + 2] = p2; }
            if (idx + 3 < N_NODES) { g_rowptr[idx + 3] = p3; g_cursor[idx + 3] = p3; }
        }
        int chunk_total = s_warp[31];
        __syncthreads();
        if (tid == 0) s_carry += chunk_total;
        __syncthreads();
    }
    if (tid == 0) g_rowptr[N_NODES] = s_carry;
}

__global__ void fill_kernel(const int* __restrict__ src,
                            const int* __restrict__ dst, int E) {
    int t = blockIdx.x * blockDim.x + threadIdx.x;
    int e = t * 4;
    if (e + 3 < E) {
        int4 d = __ldg(reinterpret_cast<const int4*>(dst + e));
        int4 s = __ldg(reinterpret_cast<const int4*>(src + e));
        int p0 = atomicAdd(&g_cursor[d.x], 1); g_csrc[p0] = s.x;
        int p1 = atomicAdd(&g_cursor[d.y], 1); g_csrc[p1] = s.y;
        int p2 = atomicAdd(&g_cursor[d.z], 1); g_csrc[p2] = s.z;
        int p3 = atomicAdd(&g_cursor[d.w], 1); g_csrc[p3] = s.w;
    } else {
        for (; e < E; e++) {
            int d = __ldg(dst + e);
            int pos = atomicAdd(&g_cursor[d], 1);
            g_csrc[pos] = __ldg(src + e);
        }
    }
}

// ---------------------------------------------------------------------------
// Aggregate (R9, unchanged): one warp per node, 16-deep MLP gather.
// ---------------------------------------------------------------------------
__global__ void __launch_bounds__(256)
aggregate_kernel(const float4* __restrict__ x, float4* __restrict__ agg) {
    int warp = (blockIdx.x * blockDim.x + threadIdx.x) >> 5;
    if (warp >= N_NODES) return;
    int lane = threadIdx.x & 31;
    int beg = __ldg(g_rowptr + warp);
    int end = __ldg(g_rowptr + warp + 1);

    float4 a = make_float4(0.f, 0.f, 0.f, 0.f);
    int i = beg;
    for (; i + 16 <= end; i += 16) {
        int s[16];
        #pragma unroll
        for (int u = 0; u < 16; u++) s[u] = __ldg(g_csrc + i + u);
        float4 v[16];
        #pragma unroll
        for (int u = 0; u < 16; u++) v[u] = __ldg(x + s[u] * D4 + lane);
        #pragma unroll
        for (int u = 0; u < 16; u++) {
            a.x += v[u].x; a.y += v[u].y; a.z += v[u].z; a.w += v[u].w;
        }
    }
    for (; i + 4 <= end; i += 4) {
        int s[4];
        #pragma unroll
        for (int u = 0; u < 4; u++) s[u] = __ldg(g_csrc + i + u);
        float4 v[4];
        #pragma unroll
        for (int u = 0; u < 4; u++) v[u] = __ldg(x + s[u] * D4 + lane);
        #pragma unroll
        for (int u = 0; u < 4; u++) {
            a.x += v[u].x; a.y += v[u].y; a.z += v[u].z; a.w += v[u].w;
        }
    }
    for (; i < end; i++) {
        int s = __ldg(g_csrc + i);
        float4 v = __ldg(x + s * D4 + lane);
        a.x += v.x; a.y += v.y; a.z += v.z; a.w += v.w;
    }
    agg[warp * D4 + lane] = a;
}

// ---------------------------------------------------------------------------
// Persistent GEMM: NPB=80, 10 m-rows/thread (crossbar < fma -> fma-bound),
// software-pipelined staging, full Wl+Wr smem-resident.
// MODE 0: LayerNorm -> ReLU ; MODE 1: ReLU ; MODE 2: identity
// ---------------------------------------------------------------------------
template <int MODE>
__global__ void __launch_bounds__(GTHREADS)
gemm_persist(const float4* __restrict__ agg,
             const float4* __restrict__ hin,
             const float* __restrict__ Wl,
             const float* __restrict__ bl,
             const float* __restrict__ Wr,
             const float* __restrict__ lng,
             const float* __restrict__ lnb,
             float* __restrict__ out) {
    extern __shared__ float4 smem[];
    float4* wl_s = smem;                       // 64 * WSTRIDE
    float4* wr_s = smem + 64 * WSTRIDE;        // 64 * WSTRIDE
    float4* s_in = smem + 2 * 64 * WSTRIDE;    // NPB * 64
    float*  s_mu = reinterpret_cast<float*>(s_in + NPB * 64);
    float*  s_rs = s_mu + NPB;

    const int tid = threadIdx.x;
    const int jh = tid & 63;
    const int j0 = 2 * jh;
    const int mg = tid >> 6;       // 0..7
    const int mbase = mg * MPT;
    const int lane = tid & 31;

    {
        const float4* Wl4 = reinterpret_cast<const float4*>(Wl);
        const float4* Wr4 = reinterpret_cast<const float4*>(Wr);
        #pragma unroll
        for (int idx = tid; idx < 128 * 32; idx += GTHREADS) {
            int j = idx >> 5, k4 = idx & 31;
            int soff = (j >> 1) * WSTRIDE + 2 * k4 + (j & 1);
            wl_s[soff] = __ldg(Wl4 + idx);
            wr_s[soff] = __ldg(Wr4 + idx);
        }
    }
    const unsigned long long bias_a = pack2(__ldg(bl + j0), 0.0f);
    const unsigned long long bias_b = pack2(__ldg(bl + j0 + 1), 0.0f);
    const float ga = __ldg(lng + j0), gb = __ldg(lng + j0 + 1);
    const float ba = __ldg(lnb + j0), bb = __ldg(lnb + j0 + 1);

    const ulonglong2* s_u = reinterpret_cast<const ulonglong2*>(s_in);

    // staging prefetch: thread owns s_in slots tid + t*GTHREADS, t in [0,10)
    float4 pf[MPT];
    {
        const int n0 = blockIdx.x * NPB;
        #pragma unroll
        for (int t = 0; t < MPT; t++) {
            int i = tid + t * GTHREADS;
            int m = i >> 6, q = i & 63;
            int n = n0 + m;
            if (n >= N_NODES) n = N_NODES - 1;
            pf[t] = (q < 32) ? __ldg(agg + n * D4 + q)
                             : __ldg(hin + n * D4 + (q - 32));
        }
    }

    for (int tile = blockIdx.x; tile < NTILES; tile += GGRID) {
        const int n0 = tile * NPB;
        __syncthreads();  // s_in free (prev tile fully consumed)

        #pragma unroll
        for (int t = 0; t < MPT; t++) s_in[tid + t * GTHREADS] = pf[t];
        __syncthreads();

        {
            int nt = tile + GGRID;
            if (nt < NTILES) {
                const int nn0 = nt * NPB;
                #pragma unroll
                for (int t = 0; t < MPT; t++) {
                    int i = tid + t * GTHREADS;
                    int m = i >> 6, q = i & 63;
                    int n = nn0 + m;
                    if (n >= N_NODES) n = N_NODES - 1;
                    pf[t] = (q < 32) ? __ldg(agg + n * D4 + q)
                                     : __ldg(hin + n * D4 + (q - 32));
                }
            }
        }

        unsigned long long acc2[MPT][2];
        #pragma unroll
        for (int m = 0; m < MPT; m++) { acc2[m][0] = bias_a; acc2[m][1] = bias_b; }

        #pragma unroll 4
        for (int k4 = 0; k4 < 32; k4++) {
            ulonglong2 wa = *reinterpret_cast<const ulonglong2*>(&wl_s[jh * WSTRIDE + 2 * k4]);
            ulonglong2 wb = *reinterpret_cast<const ulonglong2*>(&wl_s[jh * WSTRIDE + 2 * k4 + 1]);
            #pragma unroll
            for (int m = 0; m < MPT; m++) {
                ulonglong2 v = s_u[(mbase + m) * 64 + k4];
                fma2(acc2[m][0], wa.x, v.x);
                fma2(acc2[m][0], wa.y, v.y);
                fma2(acc2[m][1], wb.x, v.x);
                fma2(acc2[m][1], wb.y, v.y);
            }
        }
        #pragma unroll 4
        for (int k4 = 0; k4 < 32; k4++) {
            ulonglong2 wa = *reinterpret_cast<const ulonglong2*>(&wr_s[jh * WSTRIDE + 2 * k4]);
            ulonglong2 wb = *reinterpret_cast<const ulonglong2*>(&wr_s[jh * WSTRIDE + 2 * k4 + 1]);
            #pragma unroll
            for (int m = 0; m < MPT; m++) {
                ulonglong2 v = s_u[(mbase + m) * 64 + 32 + k4];
                fma2(acc2[m][0], wa.x, v.x);
                fma2(acc2[m][0], wa.y, v.y);
                fma2(acc2[m][1], wb.x, v.x);
                fma2(acc2[m][1], wb.y, v.y);
            }
        }

        if (MODE == 0) {
            __syncthreads();
            float* s_f = reinterpret_cast<float*>(s_in);  // [node][132]
            #pragma unroll
            for (int m = 0; m < MPT; m++) {
                float2 p = make_float2(sum2(acc2[m][0]), sum2(acc2[m][1]));
                *reinterpret_cast<float2*>(&s_f[(mbase + m) * 132 + j0]) = p;
            }
            __syncthreads();

            int wid = tid >> 5;  // 0..15, each handles 5 rows
            #pragma unroll
            for (int q = 0; q < 5; q++) {
                int r = wid * 5 + q;
                float v0 = s_f[r * 132 + lane];
                float v1 = s_f[r * 132 + lane + 32];
                float v2 = s_f[r * 132 + lane + 64];
                float v3 = s_f[r * 132 + lane + 96];
                float s  = v0 + v1 + v2 + v3;
                float ss = v0 * v0 + v1 * v1 + v2 * v2 + v3 * v3;
                #pragma unroll
                for (int o = 16; o > 0; o >>= 1) {
                    s  += __shfl_down_sync(0xFFFFFFFFu, s, o);
                    ss += __shfl_down_sync(0xFFFFFFFFu, ss, o);
                }
                if (lane == 0) {
                    float mu  = s * (1.0f / 128.0f);
                    float var = ss * (1.0f / 128.0f) - mu * mu;
                    s_mu[r] = mu;
                    s_rs[r] = rsqrtf(var + 1e-5f);
                }
            }
            __syncthreads();

            #pragma unroll
            for (int m = 0; m < MPT; m++) {
                int n = n0 + mbase + m;
                if (n < N_NODES) {
                    int r = mbase + m;
                    float2 p = *reinterpret_cast<float2*>(&s_f[r * 132 + j0]);
                    float va = fmaxf((p.x - s_mu[r]) * s_rs[r] * ga + ba, 0.0f);
                    float vb = fmaxf((p.y - s_mu[r]) * s_rs[r] * gb + bb, 0.0f);
                    *reinterpret_cast<float2*>(&out[n * D + j0]) = make_float2(va, vb);
                }
            }
        } else {
            #pragma unroll
            for (int m = 0; m < MPT; m++) {
                int n = n0 + mbase + m;
                if (n < N_NODES) {
                    float va = sum2(acc2[m][0]);
                    float vb = sum2(acc2[m][1]);
                    if (MODE == 1) { va = fmaxf(va, 0.0f); vb = fmaxf(vb, 0.0f); }
                    *reinterpret_cast<float2*>(&out[n * D + j0]) = make_float2(va, vb);
                }
            }
        }
    }
}

// ---------------------------------------------------------------------------
// Launch: dummy (ncu alignment) + CSR build once, then 3 x (agg -> gemm)
// ---------------------------------------------------------------------------
extern "C" void kernel_launch(void* const* d_in, const int* in_sizes, int n_in,
                              void* d_out, int out_size) {
    const float4* x   = (const float4*)d_in[0];
    const int*    ei  = (const int*)d_in[1];
    const int E       = in_sizes[1] / 2;
    const int* src = ei;
    const int* dst = ei + E;

    const float* Wl0 = (const float*)d_in[2];
    const float* bl0 = (const float*)d_in[3];
    const float* Wr0 = (const float*)d_in[4];
    const float* Wl1 = (const float*)d_in[5];
    const float* bl1 = (const float*)d_in[6];
    const float* Wr1 = (const float*)d_in[7];
    const float* Wl2 = (const float*)d_in[8];
    const float* bl2 = (const float*)d_in[9];
    const float* Wr2 = (const float*)d_in[10];
    const float* lng = (const float*)d_in[11];
    const float* lnb = (const float*)d_in[12];

    float4 *agg, *h1, *h2;
    int* degp;
    cudaGetSymbolAddress((void**)&agg, g_agg);
    cudaGetSymbolAddress((void**)&h1, g_h1);
    cudaGetSymbolAddress((void**)&h2, g_h2);
    cudaGetSymbolAddress((void**)&degp, g_deg);

    float* out = (float*)d_out;

    cudaFuncSetAttribute(gemm_persist<0>, cudaFuncAttributeMaxDynamicSharedMemorySize, SMEM_BYTES);
    cudaFuncSetAttribute(gemm_persist<1>, cudaFuncAttributeMaxDynamicSharedMemorySize, SMEM_BYTES);
    cudaFuncSetAttribute(gemm_persist<2>, cudaFuncAttributeMaxDynamicSharedMemorySize, SMEM_BYTES);

    const int edge4_blocks = ((E + 3) / 4 + 255) / 256;
    const int agg_blocks   = (N_NODES * 32 + 255) / 256;  // warp per node

    // ---- CSR build (once; reused by all 3 layers) ----
    cudaMemsetAsync(degp, 0, N_NODES * sizeof(int));
    dummy_kernel<<<1, 32>>>();   // aligns ncu -s 5 onto gemm_persist<0>
    hist_kernel<<<edge4_blocks, 256>>>(dst, E);
    scan_kernel<<<1, 1024>>>();
    fill_kernel<<<edge4_blocks, 256>>>(src, dst, E);

    // ---- layer 0: conv -> LN -> ReLU ----
    aggregate_kernel<<<agg_blocks, 256>>>(x, agg);
    gemm_persist<0><<<GGRID, GTHREADS, SMEM_BYTES>>>(agg, x, Wl0, bl0, Wr0, lng, lnb, (float*)h1);

    // ---- layer 1: conv -> ReLU ----
    aggregate_kernel<<<agg_blocks, 256>>>((const float4*)h1, agg);
    gemm_persist<1><<<GGRID, GTHREADS, SMEM_BYTES>>>(agg, (const float4*)h1, Wl1, bl1, Wr1, lng, lnb, (float*)h2);

    // ---- layer 2: conv (no activation) ----
    aggregate_kernel<<<agg_blocks, 256>>>((const float4*)h2, agg);
    gemm_persist<2><<<GGRID, GTHREADS, SMEM_BYTES>>>(agg, (const float4*)h2, Wl2, bl2, Wr2, lng, lnb, out);
}

// round 15
// speedup vs baseline: 1.1495x; 1.1495x over previous
#include <cuda_runtime.h>

#define N_NODES 50000
#define E_EDGES 800000
#define D 128
#define D4 32      // D in float4 units
#define NPB 88     // nodes per tile (11 m-rows per thread)
#define MPT 11     // m rows per thread
#define PF_N 6     // prefetched staging slots per thread (of 11)
#define NSLOTS 11  // staging slots per thread (NPB*64/GTHREADS)
#define NTILES ((N_NODES + NPB - 1) / NPB)
#define GTHREADS 512
#define GGRID 152
#define WSTRIDE 65 // float4 per j-pair row in weight smem (odd -> conflict-free)

// smem: wl_s[64*65] | wr_s[64*65] | s_in[NPB*64] | mu[NPB] | rs[NPB]
#define SMEM_F4 (2 * 64 * WSTRIDE + NPB * 64)
#define SMEM_BYTES (SMEM_F4 * 16 + 2 * NPB * 4)

// Scratch (allocation-free rule: __device__ globals)
__device__ float4 g_agg[N_NODES * D4];
__device__ float4 g_h1[N_NODES * D4];
__device__ float4 g_h2[N_NODES * D4];
__device__ int    g_deg[N_NODES];
__device__ int    g_rowptr[N_NODES + 1];
__device__ int    g_cursor[N_NODES];
__device__ int    g_csrc[E_EDGES];

// ---------------------------------------------------------------------------
// packed f32x2 helpers
// ---------------------------------------------------------------------------
__device__ __forceinline__ void fma2(unsigned long long& d,
                                     unsigned long long a,
                                     unsigned long long b) {
    asm("fma.rn.f32x2 %0, %1, %2, %0;" : "+l"(d) : "l"(a), "l"(b));
}
__device__ __forceinline__ unsigned long long pack2(float lo, float hi) {
    unsigned long long r;
    asm("mov.b64 %0, {%1, %2};" : "=l"(r) : "f"(lo), "f"(hi));
    return r;
}
__device__ __forceinline__ float sum2(unsigned long long v) {
    float lo, hi;
    asm("mov.b64 {%0, %1}, %2;" : "=f"(lo), "=f"(hi) : "l"(v));
    return lo + hi;
}

// ---------------------------------------------------------------------------
// CSR build: memset degrees -> histogram (x4) -> scan (x4) -> fill (x4)
// ---------------------------------------------------------------------------
__global__ void hist_kernel(const int* __restrict__ dst, int E) {
    int t = blockIdx.x * blockDim.x + threadIdx.x;
    int e = t * 4;
    if (e + 3 < E) {
        int4 d = __ldg(reinterpret_cast<const int4*>(dst + e));
        atomicAdd(&g_deg[d.x], 1);
        atomicAdd(&g_deg[d.y], 1);
        atomicAdd(&g_deg[d.z], 1);
        atomicAdd(&g_deg[d.w], 1);
    } else {
        for (; e < E; e++) atomicAdd(&g_deg[__ldg(dst + e)], 1);
    }
}

__device__ __forceinline__ int warp_incl_scan(int v, int lane) {
    #pragma unroll
    for (int o = 1; o < 32; o <<= 1) {
        int t = __shfl_up_sync(0xFFFFFFFFu, v, o);
        if (lane >= o) v += t;
    }
    return v;
}

__global__ void __launch_bounds__(1024) scan_kernel() {
    __shared__ int s_warp[32];
    __shared__ int s_carry;
    int tid = threadIdx.x;
    int lane = tid & 31, wid = tid >> 5;
    if (tid == 0) s_carry = 0;
    __syncthreads();

    for (int base = 0; base < N_NODES; base += 4096) {
        int idx = base + tid * 4;
        int d0 = 0, d1 = 0, d2 = 0, d3 = 0;
        if (idx + 3 < N_NODES) {
            int4 t4 = *reinterpret_cast<const int4*>(g_deg + idx);
            d0 = t4.x; d1 = t4.y; d2 = t4.z; d3 = t4.w;
        } else {
            if (idx + 0 < N_NODES) d0 = g_deg[idx + 0];
            if (idx + 1 < N_NODES) d1 = g_deg[idx + 1];
            if (idx + 2 < N_NODES) d2 = g_deg[idx + 2];
            if (idx + 3 < N_NODES) d3 = g_deg[idx + 3];
        }
        int tsum = d0 + d1 + d2 + d3;
        int incl = warp_incl_scan(tsum, lane);
        if (lane == 31) s_warp[wid] = incl;
        __syncthreads();
        if (wid == 0) {
            int w = s_warp[lane];
            w = warp_incl_scan(w, lane);
            s_warp[lane] = w;
        }
        __syncthreads();
        int off = s_carry + ((wid > 0) ? s_warp[wid - 1] : 0) + incl - tsum;
        int p0 = off, p1 = off + d0, p2 = p1 + d1, p3 = p2 + d2;
        if (idx + 3 < N_NODES) {
            int4 rp = make_int4(p0, p1, p2, p3);
            *reinterpret_cast<int4*>(g_rowptr + idx) = rp;
            *reinterpret_cast<int4*>(g_cursor + idx) = rp;
        } else {
            if (idx + 0 < N_NODES) { g_rowptr[idx + 0] = p0; g_cursor[idx + 0] = p0; }
            if (idx + 1 < N_NODES) { g_rowptr[idx + 1] = p1; g_cursor[idx + 1] = p1; }
            if (idx + 2 < N_NODES) { g_rowptr[idx + 2] = p2; g_cursor[idx + 2] = p2; }
            if (idx + 3 < N_NODES) { g_rowptr[idx + 3] = p3; g_cursor[idx + 3] = p3; }
        }
        int chunk_total = s_warp[31];
        __syncthreads();
        if (tid == 0) s_carry += chunk_total;
        __syncthreads();
    }
    if (tid == 0) g_rowptr[N_NODES] = s_carry;
}

__global__ void fill_kernel(const int* __restrict__ src,
                            const int* __restrict__ dst, int E) {
    int t = blockIdx.x * blockDim.x + threadIdx.x;
    int e = t * 4;
    if (e + 3 < E) {
        int4 d = __ldg(reinterpret_cast<const int4*>(dst + e));
        int4 s = __ldg(reinterpret_cast<const int4*>(src + e));
        int p0 = atomicAdd(&g_cursor[d.x], 1); g_csrc[p0] = s.x;
        int p1 = atomicAdd(&g_cursor[d.y], 1); g_csrc[p1] = s.y;
        int p2 = atomicAdd(&g_cursor[d.z], 1); g_csrc[p2] = s.z;
        int p3 = atomicAdd(&g_cursor[d.w], 1); g_csrc[p3] = s.w;
    } else {
        for (; e < E; e++) {
            int d = __ldg(dst + e);
            int pos = atomicAdd(&g_cursor[d], 1);
            g_csrc[pos] = __ldg(src + e);
        }
    }
}

// ---------------------------------------------------------------------------
// Aggregate (R9, unchanged): one warp per node, 16-deep MLP gather.
// ---------------------------------------------------------------------------
__global__ void __launch_bounds__(256)
aggregate_kernel(const float4* __restrict__ x, float4* __restrict__ agg) {
    int warp = (blockIdx.x * blockDim.x + threadIdx.x) >> 5;
    if (warp >= N_NODES) return;
    int lane = threadIdx.x & 31;
    int beg = __ldg(g_rowptr + warp);
    int end = __ldg(g_rowptr + warp + 1);

    float4 a = make_float4(0.f, 0.f, 0.f, 0.f);
    int i = beg;
    for (; i + 16 <= end; i += 16) {
        int s[16];
        #pragma unroll
        for (int u = 0; u < 16; u++) s[u] = __ldg(g_csrc + i + u);
        float4 v[16];
        #pragma unroll
        for (int u = 0; u < 16; u++) v[u] = __ldg(x + s[u] * D4 + lane);
        #pragma unroll
        for (int u = 0; u < 16; u++) {
            a.x += v[u].x; a.y += v[u].y; a.z += v[u].z; a.w += v[u].w;
        }
    }
    for (; i + 4 <= end; i += 4) {
        int s[4];
        #pragma unroll
        for (int u = 0; u < 4; u++) s[u] = __ldg(g_csrc + i + u);
        float4 v[4];
        #pragma unroll
        for (int u = 0; u < 4; u++) v[u] = __ldg(x + s[u] * D4 + lane);
        #pragma unroll
        for (int u = 0; u < 4; u++) {
            a.x += v[u].x; a.y += v[u].y; a.z += v[u].z; a.w += v[u].w;
        }
    }
    for (; i < end; i++) {
        int s = __ldg(g_csrc + i);
        float4 v = __ldg(x + s * D4 + lane);
        a.x += v.x; a.y += v.y; a.z += v.z; a.w += v.w;
    }
    agg[warp * D4 + lane] = a;
}

// ---------------------------------------------------------------------------
// Persistent GEMM: NPB=88, 11 m-rows/thread (fma-bound: crossbar 19.4K vs
// fma 22.5K cyc/tile), partial register prefetch (6 of 11 staging slots) to
// stay under the 128-reg ceiling. Full Wl+Wr smem-resident.
// MODE 0: LayerNorm -> ReLU ; MODE 1: ReLU ; MODE 2: identity
// ---------------------------------------------------------------------------
template <int MODE>
__global__ void __launch_bounds__(GTHREADS)
gemm_persist(const float4* __restrict__ agg,
             const float4* __restrict__ hin,
             const float* __restrict__ Wl,
             const float* __restrict__ bl,
             const float* __restrict__ Wr,
             const float* __restrict__ lng,
             const float* __restrict__ lnb,
             float* __restrict__ out) {
    extern __shared__ float4 smem[];
    float4* wl_s = smem;                       // 64 * WSTRIDE
    float4* wr_s = smem + 64 * WSTRIDE;        // 64 * WSTRIDE
    float4* s_in = smem + 2 * 64 * WSTRIDE;    // NPB * 64
    float*  s_mu = reinterpret_cast<float*>(s_in + NPB * 64);
    float*  s_rs = s_mu + NPB;

    const int tid = threadIdx.x;
    const int jh = tid & 63;
    const int j0 = 2 * jh;
    const int mg = tid >> 6;       // 0..7
    const int mbase = mg * MPT;
    const int lane = tid & 31;

    {
        const float4* Wl4 = reinterpret_cast<const float4*>(Wl);
        const float4* Wr4 = reinterpret_cast<const float4*>(Wr);
        #pragma unroll
        for (int idx = tid; idx < 128 * 32; idx += GTHREADS) {
            int j = idx >> 5, k4 = idx & 31;
            int soff = (j >> 1) * WSTRIDE + 2 * k4 + (j & 1);
            wl_s[soff] = __ldg(Wl4 + idx);
            wr_s[soff] = __ldg(Wr4 + idx);
        }
    }
    const unsigned long long bias_a = pack2(__ldg(bl + j0), 0.0f);
    const unsigned long long bias_b = pack2(__ldg(bl + j0 + 1), 0.0f);
    const float ga = __ldg(lng + j0), gb = __ldg(lng + j0 + 1);
    const float ba = __ldg(lnb + j0), bb = __ldg(lnb + j0 + 1);

    const ulonglong2* s_u = reinterpret_cast<const ulonglong2*>(s_in);

    // helper to load staging slot t of a tile
    auto stage_ld = [&](int tile_n0, int t) -> float4 {
        int i = tid + t * GTHREADS;
        int m = i >> 6, q = i & 63;
        int n = tile_n0 + m;
        if (n >= N_NODES) n = N_NODES - 1;
        return (q < 32) ? __ldg(agg + n * D4 + q)
                        : __ldg(hin + n * D4 + (q - 32));
    };

    // prefetch first PF_N slots of the first tile
    float4 pf[PF_N];
    {
        const int n0 = blockIdx.x * NPB;
        #pragma unroll
        for (int t = 0; t < PF_N; t++) pf[t] = stage_ld(n0, t);
    }

    for (int tile = blockIdx.x; tile < NTILES; tile += GGRID) {
        const int n0 = tile * NPB;
        __syncthreads();  // s_in free (prev tile fully consumed)

        // commit: issue non-prefetched loads first, then store prefetched
        {
            float4 dv[NSLOTS - PF_N];
            #pragma unroll
            for (int t = PF_N; t < NSLOTS; t++) dv[t - PF_N] = stage_ld(n0, t);
            #pragma unroll
            for (int t = 0; t < PF_N; t++) s_in[tid + t * GTHREADS] = pf[t];
            #pragma unroll
            for (int t = PF_N; t < NSLOTS; t++) s_in[tid + t * GTHREADS] = dv[t - PF_N];
        }
        __syncthreads();

        // prefetch NEXT tile (consumed only after the mainloop + barriers)
        {
            int nt = tile + GGRID;
            if (nt < NTILES) {
                const int nn0 = nt * NPB;
                #pragma unroll
                for (int t = 0; t < PF_N; t++) pf[t] = stage_ld(nn0, t);
            }
        }

        unsigned long long acc2[MPT][2];
        #pragma unroll
        for (int m = 0; m < MPT; m++) { acc2[m][0] = bias_a; acc2[m][1] = bias_b; }

        #pragma unroll 4
        for (int k4 = 0; k4 < 32; k4++) {
            ulonglong2 wa = *reinterpret_cast<const ulonglong2*>(&wl_s[jh * WSTRIDE + 2 * k4]);
            ulonglong2 wb = *reinterpret_cast<const ulonglong2*>(&wl_s[jh * WSTRIDE + 2 * k4 + 1]);
            #pragma unroll
            for (int m = 0; m < MPT; m++) {
                ulonglong2 v = s_u[(mbase + m) * 64 + k4];
                fma2(acc2[m][0], wa.x, v.x);
                fma2(acc2[m][0], wa.y, v.y);
                fma2(acc2[m][1], wb.x, v.x);
                fma2(acc2[m][1], wb.y, v.y);
            }
        }
        #pragma unroll 4
        for (int k4 = 0; k4 < 32; k4++) {
            ulonglong2 wa = *reinterpret_cast<const ulonglong2*>(&wr_s[jh * WSTRIDE + 2 * k4]);
            ulonglong2 wb = *reinterpret_cast<const ulonglong2*>(&wr_s[jh * WSTRIDE + 2 * k4 + 1]);
            #pragma unroll
            for (int m = 0; m < MPT; m++) {
                ulonglong2 v = s_u[(mbase + m) * 64 + 32 + k4];
                fma2(acc2[m][0], wa.x, v.x);
                fma2(acc2[m][0], wa.y, v.y);
                fma2(acc2[m][1], wb.x, v.x);
                fma2(acc2[m][1], wb.y, v.y);
            }
        }

        if (MODE == 0) {
            __syncthreads();
            float* s_f = reinterpret_cast<float*>(s_in);  // [node][132]
            #pragma unroll
            for (int m = 0; m < MPT; m++) {
                float2 p = make_float2(sum2(acc2[m][0]), sum2(acc2[m][1]));
                *reinterpret_cast<float2*>(&s_f[(mbase + m) * 132 + j0]) = p;
            }
            __syncthreads();

            int wid = tid >> 5;  // 0..15, each handles up to 6 rows
            #pragma unroll
            for (int q = 0; q < 6; q++) {
                int r = wid * 6 + q;
                if (r < NPB) {
                    float v0 = s_f[r * 132 + lane];
                    float v1 = s_f[r * 132 + lane + 32];
                    float v2 = s_f[r * 132 + lane + 64];
                    float v3 = s_f[r * 132 + lane + 96];
                    float s  = v0 + v1 + v2 + v3;
                    float ss = v0 * v0 + v1 * v1 + v2 * v2 + v3 * v3;
                    #pragma unroll
                    for (int o = 16; o > 0; o >>= 1) {
                        s  += __shfl_down_sync(0xFFFFFFFFu, s, o);
                        ss += __shfl_down_sync(0xFFFFFFFFu, ss, o);
                    }
                    if (lane == 0) {
                        float mu  = s * (1.0f / 128.0f);
                        float var = ss * (1.0f / 128.0f) - mu * mu;
                        s_mu[r] = mu;
                        s_rs[r] = rsqrtf(var + 1e-5f);
                    }
                }
            }
            __syncthreads();

            #pragma unroll
            for (int m = 0; m < MPT; m++) {
                int n = n0 + mbase + m;
                if (n < N_NODES) {
                    int r = mbase + m;
                    float2 p = *reinterpret_cast<float2*>(&s_f[r * 132 + j0]);
                    float va = fmaxf((p.x - s_mu[r]) * s_rs[r] * ga + ba, 0.0f);
                    float vb = fmaxf((p.y - s_mu[r]) * s_rs[r] * gb + bb, 0.0f);
                    *reinterpret_cast<float2*>(&out[n * D + j0]) = make_float2(va, vb);
                }
            }
        } else {
            #pragma unroll
            for (int m = 0; m < MPT; m++) {
                int n = n0 + mbase + m;
                if (n < N_NODES) {
                    float va = sum2(acc2[m][0]);
                    float vb = sum2(acc2[m][1]);
                    if (MODE == 1) { va = fmaxf(va, 0.0f); vb = fmaxf(vb, 0.0f); }
                    *reinterpret_cast<float2*>(&out[n * D + j0]) = make_float2(va, vb);
                }
            }
        }
    }
}

// ---------------------------------------------------------------------------
// Launch: CSR build once, then 3 x (aggregate -> persistent gemm)
// ---------------------------------------------------------------------------
extern "C" void kernel_launch(void* const* d_in, const int* in_sizes, int n_in,
                              void* d_out, int out_size) {
    const float4* x   = (const float4*)d_in[0];
    const int*    ei  = (const int*)d_in[1];
    const int E       = in_sizes[1] / 2;
    const int* src = ei;
    const int* dst = ei + E;

    const float* Wl0 = (const float*)d_in[2];
    const float* bl0 = (const float*)d_in[3];
    const float* Wr0 = (const float*)d_in[4];
    const float* Wl1 = (const float*)d_in[5];
    const float* bl1 = (const float*)d_in[6];
    const float* Wr1 = (const float*)d_in[7];
    const float* Wl2 = (const float*)d_in[8];
    const float* bl2 = (const float*)d_in[9];
    const float* Wr2 = (const float*)d_in[10];
    const float* lng = (const float*)d_in[11];
    const float* lnb = (const float*)d_in[12];

    float4 *agg, *h1, *h2;
    int* degp;
    cudaGetSymbolAddress((void**)&agg, g_agg);
    cudaGetSymbolAddress((void**)&h1, g_h1);
    cudaGetSymbolAddress((void**)&h2, g_h2);
    cudaGetSymbolAddress((void**)&degp, g_deg);

    float* out = (float*)d_out;

    cudaFuncSetAttribute(gemm_persist<0>, cudaFuncAttributeMaxDynamicSharedMemorySize, SMEM_BYTES);
    cudaFuncSetAttribute(gemm_persist<1>, cudaFuncAttributeMaxDynamicSharedMemorySize, SMEM_BYTES);
    cudaFuncSetAttribute(gemm_persist<2>, cudaFuncAttributeMaxDynamicSharedMemorySize, SMEM_BYTES);

    const int edge4_blocks = ((E + 3) / 4 + 255) / 256;
    const int agg_blocks   = (N_NODES * 32 + 255) / 256;  // warp per node

    // ---- CSR build (once; reused by all 3 layers) ----
    cudaMemsetAsync(degp, 0, N_NODES * sizeof(int));
    hist_kernel<<<edge4_blocks, 256>>>(dst, E);
    scan_kernel<<<1, 1024>>>();
    fill_kernel<<<edge4_blocks, 256>>>(src, dst, E);

    // ---- layer 0: conv -> LN -> ReLU ----
    aggregate_kernel<<<agg_blocks, 256>>>(x, agg);
    gemm_persist<0><<<GGRID, GTHREADS, SMEM_BYTES>>>(agg, x, Wl0, bl0, Wr0, lng, lnb, (float*)h1);

    // ---- layer 1: conv -> ReLU ----
    aggregate_kernel<<<agg_blocks, 256>>>((const float4*)h1, agg);
    gemm_persist<1><<<GGRID, GTHREADS, SMEM_BYTES>>>(agg, (const float4*)h1, Wl1, bl1, Wr1, lng, lnb, (float*)h2);

    // ---- layer 2: conv (no activation) ----
    aggregate_kernel<<<agg_blocks, 256>>>((const float4*)h2, agg);
    gemm_persist<2><<<GGRID, GTHREADS, SMEM_BYTES>>>(agg, (const float4*)h2, Wl2, bl2, Wr2, lng, lnb, out);
}